// round 16
// baseline (speedup 1.0000x reference)
#include <cuda_runtime.h>
#include <cuda_fp16.h>
#include <cstdint>

#define TT 4
#define NTOK 8192
#define DD 1024
#define EE 8
#define EFF 512
#define TOPK 2
#define CAP (NTOK*TOPK)
#define MTOK 16
#define MR 64                     // A rows per CTA (16 slots x 4 t)
#define KCH 64
#define SA 72
#define ATB (MR*SA*2)             // 9216  B per A tile (64 rows x 144B)
#define BTB (128*SA*2)            // 18432 B per B tile (128 rows x 144B)
#define XSZ (TT*NTOK*DD)
#define USZ (EE*EFF*DD)
#define DSZ (EE*DD*EFF)
#define EPS 132
#define RSC (1.0f/2048.0f)

__device__ int g_count[EE];
__device__ int g_list[EE*CAP];
__device__ __half g_xl[(size_t)2*XSZ];   // x0, x1s(<<11)
__device__ __half g_uw[(size_t)2*USZ];   // u0, u1s
__device__ __half g_dw[(size_t)2*DSZ];   // d0, d1s
__device__ __half g_spk[(size_t)CAP*TT*EFF];

static __device__ __forceinline__ uint32_t s2u(const void* p) {
    uint32_t a;
    asm("{ .reg .u64 t; cvta.to.shared.u64 t, %1; cvt.u32.u64 %0, t; }" : "=r"(a) : "l"(p));
    return a;
}
#define CP16(dst, src) asm volatile("cp.async.cg.shared.global [%0], [%1], 16;" \
    :: "r"(dst), "l"(src) : "memory")
#define CPCOMMIT() asm volatile("cp.async.commit_group;" ::: "memory")
#define CPWAIT(n)  asm volatile("cp.async.wait_group %0;" :: "n"(n) : "memory")
#define LDSM4(r0,r1,r2,r3,addr) asm volatile( \
    "ldmatrix.sync.aligned.m8n8.x4.shared.b16 {%0,%1,%2,%3}, [%4];" \
    : "=r"(r0),"=r"(r1),"=r"(r2),"=r"(r3) : "r"(addr))
#define MMA(c, a, b) asm volatile( \
    "mma.sync.aligned.m16n8k16.row.col.f32.f16.f16.f32 " \
    "{%0,%1,%2,%3},{%4,%5,%6,%7},{%8,%9},{%0,%1,%2,%3};" \
    : "+f"((c)[0]),"+f"((c)[1]),"+f"((c)[2]),"+f"((c)[3]) \
    : "r"((a)[0]),"r"((a)[1]),"r"((a)[2]),"r"((a)[3]), "r"((b)[0]),"r"((b)[1]))

static __device__ __forceinline__ void lif4(float v0, float v1, float v2, float v3,
                                            float &s0, float &s1, float &s2, float &s3) {
    float m = v0;     s0 = (m > 1.0f) ? 1.0f : 0.0f; m -= s0;
    m = 0.9f*m + v1;  s1 = (m > 1.0f) ? 1.0f : 0.0f; m -= s1;
    m = 0.9f*m + v2;  s2 = (m > 1.0f) ? 1.0f : 0.0f; m -= s2;
    m = 0.9f*m + v3;  s3 = (m > 1.0f) ? 1.0f : 0.0f;
}

__global__ void reset_kernel() { if (threadIdx.x < EE) g_count[threadIdx.x] = 0; }

__global__ void route_kernel(const int* __restrict__ idx) {
    int n = blockIdx.x * blockDim.x + threadIdx.x;
    if (n >= NTOK) return;
    #pragma unroll
    for (int k = 0; k < TOPK; ++k) {
        int e = idx[n*TOPK + k];
        int p = atomicAdd(&g_count[e], 1);
        g_list[e*CAP + p] = (n << 1) | k;
    }
}

static __device__ __forceinline__ uint32_t hbits(__half h) {
    return (uint32_t)__half_as_ushort(h);
}

#define NX8 (XSZ/8)
#define NU8 (USZ/8)
#define ND8 (DSZ/8)
__global__ void split_all_kernel(const float* __restrict__ x,
                                 const float* __restrict__ up,
                                 const float* __restrict__ dw) {
    size_t i = (size_t)blockIdx.x * blockDim.x + threadIdx.x;
    if (i >= (size_t)(NX8 + NU8 + ND8)) return;
    const float* src;
    __half* d;
    size_t sz;
    if (i < NX8)            { src = x  + i*8;           d = g_xl + i*8;              sz = XSZ; }
    else if (i < NX8 + NU8) { size_t j = i - NX8;       src = up + j*8; d = g_uw + j*8; sz = USZ; }
    else                    { size_t j = i - NX8 - NU8; src = dw + j*8; d = g_dw + j*8; sz = DSZ; }
    float4 v0 = ((const float4*)src)[0];
    float4 v1 = ((const float4*)src)[1];
    float a[8] = {v0.x, v0.y, v0.z, v0.w, v1.x, v1.y, v1.z, v1.w};
    uint32_t p0[4], p1[4];
    #pragma unroll
    for (int j = 0; j < 4; ++j) {
        __half h0a = __float2half_rn(a[2*j]);
        __half h0b = __float2half_rn(a[2*j+1]);
        float ra = a[2*j]   - __half2float(h0a);
        float rb = a[2*j+1] - __half2float(h0b);
        p0[j] = hbits(h0a) | (hbits(h0b) << 16);
        p1[j] = hbits(__float2half_rn(ra * 2048.0f))
              | (hbits(__float2half_rn(rb * 2048.0f)) << 16);
    }
    *(uint4*)(d)      = make_uint4(p0[0], p0[1], p0[2], p0[3]);
    *(uint4*)(d + sz) = make_uint4(p1[0], p1[1], p1[2], p1[3]);
}

// S=1: spikes = LIF(x@up^T); A {x0,x1s} (64 rows), B {u0,u1s} (128 rows)
//      combos: (x0,u0)->H; (x0,u1s),(x1s,u0)->L.  val = H + L/2048
// S=2: out += w*LIF(spk@down^T); A {spk}, B {d0,d1s}: (s,d0)->H; (s,d1s)->L
// CTA tile 64x128, warp tile 32x32, 2-stage cp.async pipeline, 2 CTAs/SM.
template<int S>
__global__ __launch_bounds__(256, 2)
void gemm_lif(const float* __restrict__ ew, float* __restrict__ out) {
    constexpr int NA = (S == 1) ? 2 : 1;
    constexpr int KTOT = (S == 1) ? DD : EFF;
    constexpr int NC = KTOT / KCH;
    constexpr size_t BSZ = (S == 1) ? (size_t)USZ : (size_t)DSZ;
    constexpr int BUF = NA*ATB + 2*BTB;
    const int e = blockIdx.z, nc = blockIdx.y;
    const int cnt = g_count[e], start = blockIdx.x * MTOK;
    if (start >= cnt) return;

    extern __shared__ char dyn[];
    const uint32_t sb = s2u(dyn);
    __shared__ int s_ent[MTOK], s_ok[MTOK], s_rb[MR];
    __shared__ float s_w[MTOK];

    const int tid = threadIdx.x, lane = tid & 31, wid = tid >> 5;
    const int wm = wid & 1, wn = wid >> 1;
    if (tid < MTOK) {
        int i = start + tid, ok = (i < cnt) ? 1 : 0;
        int ent = g_list[e*CAP + (ok ? i : cnt - 1)];
        s_ent[tid] = ent; s_ok[tid] = ok; s_w[tid] = ew[ent];
    }
    __syncthreads();
    if (tid < MR) {
        int ent = s_ent[tid >> 2];
        s_rb[tid] = (S == 1) ? ((tid & 3)*NTOK + (ent >> 1))*DD
                             : ent*(TT*EFF) + (tid & 3)*EFF;
    }
    __syncthreads();

    const size_t wbase = (S == 1) ? ((size_t)e*EFF + (size_t)nc*128)*DD
                                  : ((size_t)e*DD  + (size_t)nc*128)*EFF;
    const __half* Bp = (S == 1) ? g_uw : g_dw;

    float aH[2][4][4], aL[2][4][4];
    #pragma unroll
    for (int mi = 0; mi < 2; ++mi)
        #pragma unroll
        for (int nj = 0; nj < 4; ++nj)
            #pragma unroll
            for (int q = 0; q < 4; ++q) { aH[mi][nj][q] = 0.0f; aL[mi][nj][q] = 0.0f; }

    const uint32_t aoff = (uint32_t)((wm*32 + (lane & 15))*(SA*2) + (lane >> 4)*16);
    const uint32_t boff = (uint32_t)((wn*32 + (lane & 15))*(SA*2) + (lane >> 4)*16);

    // staging: A ops = NA*512 (tile=64rowsx8segs), B ops = 2*1024
#define STAGE_CHUNK(CK, DSTB) do {                                                     \
        const int _kb = (CK) * KCH;                                                    \
        _Pragma("unroll")                                                              \
        for (int u = 0; u < NA*2 + 8; ++u) {                                           \
            int q = u*256 + tid;                                                       \
            if (q < NA*512) {                                                          \
                int tile = q >> 9, idx = q & 511, row = idx >> 3, seg = idx & 7;       \
                const __half* src = (S == 1)                                           \
                    ? g_xl + (size_t)tile*XSZ + s_rb[row] + _kb + seg*8                \
                    : g_spk + (size_t)s_rb[row] + _kb + seg*8;                         \
                CP16((DSTB) + tile*ATB + row*(SA*2) + seg*16, src);                    \
            } else {                                                                   \
                int qq = q - NA*512;                                                   \
                int tile = qq >> 10, idx = qq & 1023, row = idx >> 3, seg = idx & 7;   \
                const __half* src = Bp + (size_t)tile*BSZ + wbase                      \
                                    + (size_t)row*KTOT + _kb + seg*8;                  \
                CP16((DSTB) + NA*ATB + tile*BTB + row*(SA*2) + seg*16, src);           \
            }                                                                          \
        }                                                                              \
        CPCOMMIT();                                                                    \
    } while (0)

    STAGE_CHUNK(0, sb);

    for (int kc = 0; kc < NC; ++kc) {
        if (kc + 1 < NC) {
            STAGE_CHUNK(kc + 1, sb + ((kc + 1) & 1) * BUF);
            CPWAIT(1);
        } else {
            CPWAIT(0);
        }
        __syncthreads();
        const uint32_t base = sb + (kc & 1) * BUF;
        #pragma unroll
        for (int k16 = 0; k16 < 4; ++k16) {
            const uint32_t ko = k16 * 32;
            uint32_t b[2][4][2];
            #pragma unroll
            for (int lb = 0; lb < 2; ++lb)
                #pragma unroll
                for (int g = 0; g < 2; ++g) {
                    uint32_t r0, r1, r2, r3;
                    LDSM4(r0, r1, r2, r3, base + NA*ATB + lb*BTB + boff + g*16*(SA*2) + ko);
                    b[lb][g*2+0][0] = r0; b[lb][g*2+0][1] = r2;
                    b[lb][g*2+1][0] = r1; b[lb][g*2+1][1] = r3;
                }
            #pragma unroll
            for (int la = 0; la < NA; ++la) {
                uint32_t a[2][4];
                #pragma unroll
                for (int mi = 0; mi < 2; ++mi)
                    LDSM4(a[mi][0], a[mi][1], a[mi][2], a[mi][3],
                          base + la*ATB + aoff + mi*16*(SA*2) + ko);
                if (la == 0) {
                    #pragma unroll
                    for (int mi = 0; mi < 2; ++mi)
                        #pragma unroll
                        for (int nj = 0; nj < 4; ++nj)
                            MMA(aH[mi][nj], a[mi], b[0][nj]);     // (0,0) -> H
                    #pragma unroll
                    for (int mi = 0; mi < 2; ++mi)
                        #pragma unroll
                        for (int nj = 0; nj < 4; ++nj)
                            MMA(aL[mi][nj], a[mi], b[1][nj]);     // (0,1s) -> L
                } else {
                    #pragma unroll
                    for (int mi = 0; mi < 2; ++mi)
                        #pragma unroll
                        for (int nj = 0; nj < 4; ++nj)
                            MMA(aL[mi][nj], a[mi], b[0][nj]);     // (1s,0) -> L
                }
            }
        }
        __syncthreads();
    }

    float* ep = (float*)dyn;
    #pragma unroll
    for (int mi = 0; mi < 2; ++mi)
        #pragma unroll
        for (int nj = 0; nj < 4; ++nj) {
            int R = wm*32 + mi*16 + (lane >> 2);
            int C = wn*32 + nj*8 + (lane & 3)*2;
            *(float2*)&ep[R*EPS + C] = make_float2(aH[mi][nj][0] + aL[mi][nj][0]*RSC,
                                                   aH[mi][nj][1] + aL[mi][nj][1]*RSC);
            *(float2*)&ep[(R+8)*EPS + C] = make_float2(aH[mi][nj][2] + aL[mi][nj][2]*RSC,
                                                       aH[mi][nj][3] + aL[mi][nj][3]*RSC);
        }
    __syncthreads();
    #pragma unroll
    for (int i = 0; i < 4; ++i) {
        int c = i*256 + tid;
        int sl = c >> 6, cp = c & 63;
        if (!s_ok[sl]) continue;
        float2 v0 = *(float2*)&ep[(sl*4+0)*EPS + cp*2];
        float2 v1 = *(float2*)&ep[(sl*4+1)*EPS + cp*2];
        float2 v2 = *(float2*)&ep[(sl*4+2)*EPS + cp*2];
        float2 v3 = *(float2*)&ep[(sl*4+3)*EPS + cp*2];
        float a0,a1,a2,a3, b0,b1,b2,b3;
        lif4(v0.x, v1.x, v2.x, v3.x, a0, a1, a2, a3);
        lif4(v0.y, v1.y, v2.y, v3.y, b0, b1, b2, b3);
        if (S == 1) {
            __half* spb = g_spk + (size_t)s_ent[sl]*(TT*EFF) + nc*128 + cp*2;
            uint32_t p0 = (a0 != 0.0f ? 0x3C00u : 0u) | (b0 != 0.0f ? 0x3C000000u : 0u);
            uint32_t p1 = (a1 != 0.0f ? 0x3C00u : 0u) | (b1 != 0.0f ? 0x3C000000u : 0u);
            uint32_t p2 = (a2 != 0.0f ? 0x3C00u : 0u) | (b2 != 0.0f ? 0x3C000000u : 0u);
            uint32_t p3 = (a3 != 0.0f ? 0x3C00u : 0u) | (b3 != 0.0f ? 0x3C000000u : 0u);
            *(uint32_t*)(spb + 0*EFF) = p0;
            *(uint32_t*)(spb + 1*EFF) = p1;
            *(uint32_t*)(spb + 2*EFF) = p2;
            *(uint32_t*)(spb + 3*EFF) = p3;
        } else {
            int n = s_ent[sl] >> 1;
            float w = s_w[sl];
            float s[4][2] = {{a0,b0},{a1,b1},{a2,b2},{a3,b3}};
            #pragma unroll
            for (int t = 0; t < 4; ++t) {
                float* ob = out + ((size_t)t*NTOK + n)*DD + nc*128 + cp*2;
                if (s[t][0] != 0.0f) atomicAdd(ob,     w);
                if (s[t][1] != 0.0f) atomicAdd(ob + 1, w);
            }
        }
    }
#undef STAGE_CHUNK
}

#define S1_SMEM (2*(2*ATB + 2*BTB))   // 110592 per CTA -> 2 CTAs/SM; >= epilogue 33792
#define S2_SMEM (2*(1*ATB + 2*BTB))   // 92160

extern "C" void kernel_launch(void* const* d_in, const int* in_sizes, int n_in,
                              void* d_out, int out_size) {
    const float* x  = (const float*)d_in[0];
    const int*   ei = (const int*)  d_in[1];
    const float* ew = (const float*)d_in[2];
    const float* up = (const float*)d_in[3];
    const float* dw = (const float*)d_in[4];
    float* out = (float*)d_out;
    (void)in_sizes; (void)n_in;

    cudaFuncSetAttribute(gemm_lif<1>, cudaFuncAttributeMaxDynamicSharedMemorySize, S1_SMEM);
    cudaFuncSetAttribute(gemm_lif<2>, cudaFuncAttributeMaxDynamicSharedMemorySize, S2_SMEM);

    cudaMemsetAsync(d_out, 0, (size_t)out_size * sizeof(float), 0);
    reset_kernel<<<1, 32>>>();
    route_kernel<<<NTOK/256, 256>>>(ei);
    split_all_kernel<<<(NX8 + NU8 + ND8 + 255)/256, 256>>>(x, up, dw);
    gemm_lif<1><<<dim3(CAP/MTOK, EFF/128, EE), 256, S1_SMEM>>>(ew, out);
    gemm_lif<2><<<dim3(CAP/MTOK, DD/128,  EE), 256, S2_SMEM>>>(ew, out);
}